// round 9
// baseline (speedup 1.0000x reference)
#include <cuda_runtime.h>

// Problem constants (fixed shapes)
#define N_SAMPLES 1024
#define L_LAYERS  60
#define C_CH      42
#define NOUT      336      // C*K
#define LC        2520     // L*C
#define NTHREADS  352
#define SOLAR_C   1361.0f
#define EPSV      1e-6f

#define PL_STRIDE (N_SAMPLES*C_CH)   // 43008 floats per layer-row

// h_t swizzled layout: row stride 80 floats, 16-layer chunk lg at offset lg*20
#define HT_STRIDE 80
#define HT_CHUNK  20

// Output offsets (tuple arrays flattened C-order, concatenated in order)
#define OFF_FDIR 0
#define OFF_FDIF (N_SAMPLES*61)
#define OFF_FUP  (2*N_SAMPLES*61)
#define OFF_FABS (3*N_SAMPLES*61)
#define OFF_RTOA (OFF_FABS + N_SAMPLES*60)
#define OFF_SDIR (OFF_RTOA + N_SAMPLES)
#define OFF_SDIF (OFF_SDIR + N_SAMPLES*60)
#define OFF_TDIR (OFF_SDIF + N_SAMPLES*60)
#define OFF_TDIF (OFF_TDIR + N_SAMPLES*60)

// Global scratch planes [plane][l][n*42+c]:
// 0=td, 1=sd, 2=rd, 3=Td, 4=Rd, 5=tf->rb_dir, 6=es->rb_dif
// (phase B: after 2b consumes tf/es, scans overwrite 5/6 with rb planes;
//  prop overwrites 0..3 with a/D/up/abs)
__device__ float g_planes[7][L_LAYERS][PL_STRIDE];

__device__ __forceinline__ float softplus_f(float x) {
    return fmaxf(x, 0.f) + __logf(1.f + __expf(-fabsf(x)));
}
__device__ __forceinline__ float frcp(float x) {
    float r; asm("rcp.approx.ftz.f32 %0, %1;" : "=f"(r) : "f"(x)); return r;
}
__device__ __forceinline__ float frcp_nr(float x) {
    float r = frcp(x);
    return r * (2.f - x * r);
}
// ---- packed f32x2 helpers ----
__device__ __forceinline__ unsigned long long dup2(float x) {
    unsigned long long r;
    asm("mov.b64 %0, {%1, %1};" : "=l"(r) : "f"(x));
    return r;
}
__device__ __forceinline__ unsigned long long pack2(float lo, float hi) {
    unsigned long long r;
    asm("mov.b64 %0, {%1, %2};" : "=l"(r) : "f"(lo), "f"(hi));
    return r;
}
__device__ __forceinline__ void unpack2(unsigned long long v, float& lo, float& hi) {
    asm("mov.b64 {%0, %1}, %2;" : "=f"(lo), "=f"(hi) : "l"(v));
}
__device__ __forceinline__ void ffma2(unsigned long long& d, unsigned long long a,
                                      unsigned long long b) {
    asm("fma.rn.f32x2 %0, %1, %2, %0;" : "+l"(d) : "l"(a), "l"(b));
}

// ============================ Kernel A: MLPs + physics ============================
struct SmemA {
    float tau[2520];
    float h_t[5120];
    float xs[600];
    float b1[64];
    float w1[128];
    float scw1_0[16];
    float beff_dir[16];
    float beff_dif[16];
    float scw2[48];
    float scb2[4];
};

__global__ __launch_bounds__(NTHREADS, 2)
void radnet_A(const float* __restrict__ x_layers,
              const float* __restrict__ x_surface,
              const float* __restrict__ w_mu,
              const float* __restrict__ od_w1,
              const float* __restrict__ od_b1,
              const float* __restrict__ od_w2,
              const float* __restrict__ od_b2,
              const float* __restrict__ sc_w1,
              const float* __restrict__ sc_b1,
              const float* __restrict__ sc_w2,
              const float* __restrict__ sc_b2)
{
    extern __shared__ __align__(16) char smem_raw[];
    SmemA* S = reinterpret_cast<SmemA*>(smem_raw);
    const int tid = threadIdx.x;
    const int n = blockIdx.x;

    const float mu_direct = __ldg(&x_surface[n*5 + 0]);
    const float wmu       = __ldg(&w_mu[0]);
    const float mu_dif0   = 1.f / (1.f + __expf(-wmu));
    const float inv_mud   = 1.f / (mu_direct + EPSV);
    const float inv_muf   = 1.f / (mu_dif0 + EPSV);

    // ---------------- setup ----------------
    {
        const float4* xsrc = reinterpret_cast<const float4*>(x_layers + (size_t)n * 600);
        float4* xdst = reinterpret_cast<float4*>(S->xs);
        for (int i = tid; i < 150; i += NTHREADS) xdst[i] = xsrc[i];
        if (tid < 64)  S->b1[tid] = od_b1[tid];
        if (tid >= 64 && tid < 192) S->w1[tid-64] = od_w1[tid-64];
        if (tid >= 192 && tid < 208) {
            int j = tid - 192;
            float w1c = sc_w1[j*2 + 1];
            float b   = sc_b1[j];
            S->scw1_0[j]   = sc_w1[j*2];
            S->beff_dir[j] = fmaf(w1c, mu_direct, b);
            S->beff_dif[j] = fmaf(w1c, mu_dif0, b);
        }
        if (tid >= 208 && tid < 256) S->scw2[tid-208] = sc_w2[tid-208];
        if (tid >= 256 && tid < 259) S->scb2[tid-256] = sc_b2[tid-256];
    }
    __syncthreads();

    // ---------------- phase 1a: transposed hidden h_t, swizzled layout ----------------
    float* h_t = S->h_t;
    for (int i = tid; i < 4096; i += NTHREADS) {
        int j = i >> 6, l = i & 63;
        float v = 0.f;
        if (l < 60) {
            float pre = fmaf(S->w1[j*2],   S->xs[l*10],
                        fmaf(S->w1[j*2+1], S->xs[l*10+1], S->b1[j]));
            v = softplus_f(pre);
        }
        h_t[j*HT_STRIDE + (l>>4)*HT_CHUNK + (l&15)] = v;
    }
    __syncthreads();

    // ---------------- phase 1b: GEMM, 4 outputs x 16 layers per thread ----------------
    float* tau = S->tau;
    {
        int og = tid >> 2; if (og >= 84) og -= 84;
        const int lg = tid & 3;
        const int c = og >> 1, half = og & 1;
        const int o0 = c*8 + half*4;
        const int l_base = lg << 4;
        const float4* w2r0 = reinterpret_cast<const float4*>(od_w2) + (o0    )*16;
        const float4* w2r1 = w2r0 + 16;
        const float4* w2r2 = w2r0 + 32;
        const float4* w2r3 = w2r0 + 48;
        float b2v[4];
        #pragma unroll
        for (int i = 0; i < 4; i++) b2v[i] = __ldg(&od_b2[o0+i]);
        const unsigned hbase = (unsigned)__cvta_generic_to_shared(h_t)
                             + (unsigned)(lg*HT_CHUNK*4);

        #pragma unroll 1
        for (int sub = 0; sub < 2; sub++) {
            const unsigned soff = (unsigned)(sub*32);
            unsigned long long acc0[4], acc1[4], acc2[4], acc3[4];
            #pragma unroll
            for (int p = 0; p < 4; p++) { acc0[p]=0ull; acc1[p]=0ull; acc2[p]=0ull; acc3[p]=0ull; }
            #pragma unroll 1
            for (int j4 = 0; j4 < 16; j4++) {
                float4 w0 = __ldg(&w2r0[j4]);
                float4 w1 = __ldg(&w2r1[j4]);
                float4 w2 = __ldg(&w2r2[j4]);
                float4 w3 = __ldg(&w2r3[j4]);
                #pragma unroll
                for (int jj = 0; jj < 4; jj++) {
                    const unsigned a = hbase + soff
                                     + (unsigned)((j4*4 + jj)*HT_STRIDE*4);
                    unsigned long long h0, h1, h2, h3;
                    asm("ld.shared.v2.u64 {%0, %1}, [%2];"
                        : "=l"(h0), "=l"(h1) : "r"(a));
                    asm("ld.shared.v2.u64 {%0, %1}, [%2];"
                        : "=l"(h2), "=l"(h3) : "r"(a + 16u));
                    const float s0 = (jj==0)?w0.x:(jj==1)?w0.y:(jj==2)?w0.z:w0.w;
                    const float s1 = (jj==0)?w1.x:(jj==1)?w1.y:(jj==2)?w1.z:w1.w;
                    const float s2 = (jj==0)?w2.x:(jj==1)?w2.y:(jj==2)?w2.z:w2.w;
                    const float s3 = (jj==0)?w3.x:(jj==1)?w3.y:(jj==2)?w3.z:w3.w;
                    unsigned long long d0 = dup2(s0), d1 = dup2(s1);
                    unsigned long long d2 = dup2(s2), d3 = dup2(s3);
                    ffma2(acc0[0], d0, h0); ffma2(acc0[1], d0, h1);
                    ffma2(acc0[2], d0, h2); ffma2(acc0[3], d0, h3);
                    ffma2(acc1[0], d1, h0); ffma2(acc1[1], d1, h1);
                    ffma2(acc1[2], d1, h2); ffma2(acc1[3], d1, h3);
                    ffma2(acc2[0], d2, h0); ffma2(acc2[1], d2, h1);
                    ffma2(acc2[2], d2, h2); ffma2(acc2[3], d2, h3);
                    ffma2(acc3[0], d3, h0); ffma2(acc3[1], d3, h1);
                    ffma2(acc3[2], d3, h2); ffma2(acc3[3], d3, h3);
                }
            }
            #pragma unroll
            for (int p = 0; p < 4; p++) {
                const int la = l_base + sub*8 + 2*p;
                const int lb = la + 1;
                float f0a, f0b, f1a, f1b, f2a, f2b, f3a, f3b;
                unpack2(acc0[p], f0a, f0b);
                unpack2(acc1[p], f1a, f1b);
                unpack2(acc2[p], f2a, f2b);
                unpack2(acc3[p], f3a, f3b);
                float va = 0.f, vb = 0.f;
                if (la < 60) {
                    const float* cona = &S->xs[la*10 + 2 + half*4];
                    va = softplus_f(f0a + b2v[0]) * cona[0]
                       + softplus_f(f1a + b2v[1]) * cona[1]
                       + softplus_f(f2a + b2v[2]) * cona[2]
                       + softplus_f(f3a + b2v[3]) * cona[3];
                }
                if (lb < 60) {
                    const float* conb = &S->xs[lb*10 + 2 + half*4];
                    vb = softplus_f(f0b + b2v[0]) * conb[0]
                       + softplus_f(f1b + b2v[1]) * conb[1]
                       + softplus_f(f2b + b2v[2]) * conb[2]
                       + softplus_f(f3b + b2v[3]) * conb[3];
                }
                va += __shfl_xor_sync(0xFFFFFFFFu, va, 4);
                vb += __shfl_xor_sync(0xFFFFFFFFu, vb, 4);
                if (half == 0) {
                    if (la < 60) tau[la*42 + c] = va;
                    if (lb < 60) tau[lb*42 + c] = vb;
                }
            }
        }
    }
    __syncthreads();

    // ---------------- phase 2: physics + split MLPs -> global planes ----------------
    const int nbase = n * C_CH;
    #pragma unroll 1
    for (int pass = 0; pass < 2; pass++) {
        float tt[4];
        #pragma unroll
        for (int r = 0; r < 4; r++) {
            int idx = tid + (pass*4 + r)*NTHREADS;
            tt[r] = tau[idx < LC ? idx : 0];
        }
        const float b20 = S->scb2[0], b21 = S->scb2[1], b22 = S->scb2[2];
        unsigned long long A0[4], A1[4], A2[4];
        #pragma unroll
        for (int r = 0; r < 4; r++) {
            A0[r] = dup2(b20); A1[r] = dup2(b21); A2[r] = dup2(b22);
        }
        #pragma unroll
        for (int j = 0; j < 16; j++) {
            float w0  = S->scw1_0[j];
            float bd  = S->beff_dir[j];
            float bf  = S->beff_dif[j];
            unsigned long long w20d = dup2(S->scw2[j]);
            unsigned long long w21d = dup2(S->scw2[16+j]);
            unsigned long long w22d = dup2(S->scw2[32+j]);
            #pragma unroll
            for (int r = 0; r < 4; r++) {
                float hp = w0 * tt[r];
                float hd = fmaxf(hp + bd, 0.f);
                float hf = fmaxf(hp + bf, 0.f);
                unsigned long long h2 = pack2(hd, hf);
                ffma2(A0[r], w20d, h2);
                ffma2(A1[r], w21d, h2);
                ffma2(A2[r], w22d, h2);
            }
        }
        #pragma unroll
        for (int r = 0; r < 4; r++) {
            int idx = tid + (pass*4 + r)*NTHREADS;
            if (idx >= LC) break;
            float a0d, a0f, a1d, a1f, a2d, a2f;
            unpack2(A0[r], a0d, a0f);
            unpack2(A1[r], a1d, a1f);
            unpack2(A2[r], a2d, a2f);
            float td = __expf(-tt[r]*inv_mud);
            float tf = __expf(-tt[r]*inv_muf);
            float m  = fmaxf(a0d, fmaxf(a1d, a2d));
            float x0 = __expf(a0d-m), x1 = __expf(a1d-m), x2 = __expf(a2d-m);
            float inv = frcp(x0+x1+x2);
            float e0d = x0*inv, e1d = x1*inv;
            m  = fmaxf(a0f, fmaxf(a1f, a2f));
            x0 = __expf(a0f-m); x1 = __expf(a1f-m); x2 = __expf(a2f-m);
            inv = frcp(x0+x1+x2);
            float e0f = x0*inv, e1f = x1*inv;
            float omtd = 1.f - td, omtf = 1.f - tf;
            const int l = idx / 42, c = idx - l*42;
            const int g = l*PL_STRIDE + nbase + c;
            g_planes[0][0][g] = td;
            g_planes[1][0][g] = omtd*e0d;
            g_planes[2][0][g] = omtd*e1d;
            g_planes[3][0][g] = fmaf(omtf, e0f, tf);
            g_planes[4][0][g] = omtf*e1f;
            g_planes[5][0][g] = tf;
            g_planes[6][0][g] = omtf*(e0f+e1f);
        }
    }
}

// ============================ Kernel B: reductions + scans ============================
#define NB_S 4                 // samples per block
#define NTHREADS_B (NB_S*C_CH) // 168
#define GRID_B (N_SAMPLES/NB_S)

__global__ __launch_bounds__(NTHREADS_B, 8)
void radnet_B(const float* __restrict__ x_surface,
              const float* __restrict__ w_spec,
              float* __restrict__ out)
{
    __shared__ float cs[C_CH];
    __shared__ float cs_sum_s;
    __shared__ float s_al[NTHREADS_B], s_dl[NTHREADS_B], s_rtoa[NTHREADS_B];

    const int tid = threadIdx.x;
    const int blk = blockIdx.x;
    const int s_loc = tid / C_CH;
    const int c = tid - s_loc * C_CH;
    const int n = blk*NB_S + s_loc;
    const int nbase = n * C_CH;

    if (tid == 0) {
        float m = -1e30f;
        for (int i = 0; i < C_CH; i++) m = fmaxf(m, w_spec[i]);
        float s = 0.f; float tmp[C_CH];
        for (int i = 0; i < C_CH; i++) { float e = __expf(w_spec[i]-m); tmp[i] = e; s += e; }
        float inv = 1.f / s; float cssum = 0.f;
        for (int i = 0; i < C_CH; i++) { float v = tmp[i]*inv; cs[i] = v; cssum += v; }
        cs_sum_s = cssum;
    }
    __syncthreads();

    const float* p_td = &g_planes[0][0][0];
    const float* p_sd = &g_planes[1][0][0];
    const float* p_rd = &g_planes[2][0][0];
    const float* p_Td = &g_planes[3][0][0];
    const float* p_Rd = &g_planes[4][0][0];
    float* p_rbd = &g_planes[5][0][0];   // tf plane, consumed by 2b then reused
    float* p_rbf = &g_planes[6][0][0];   // es plane, consumed by 2b then reused

    // ---------------- 2b: per-layer channel sums (reads tf/es/td/sd/rd) ----------------
    for (int t = tid; t < NB_S*4*60; t += NTHREADS_B) {
        int s = t / 240, rem = t - s*240;
        int arr = rem / 60, l = rem - arr*60;
        int nn = blk*NB_S + s;
        int base = l*PL_STRIDE + nn*C_CH;
        float acc = 0.f;
        if (arr == 0) {
            for (int cc = 0; cc < C_CH; cc++)
                acc = fmaf(p_sd[base+cc] + p_rd[base+cc], cs[cc], acc);
            out[OFF_SDIR + nn*60 + l] = acc;
        } else if (arr == 1) {
            for (int cc = 0; cc < C_CH; cc++)
                acc = fmaf(p_rbf[base+cc], cs[cc], acc);      // es plane
            out[OFF_SDIF + nn*60 + l] = acc;
        } else if (arr == 2) {
            for (int cc = 0; cc < C_CH; cc++)
                acc = fmaf(p_td[base+cc], cs[cc], acc);
            out[OFF_TDIR + nn*60 + l] = acc;
        } else {
            for (int cc = 0; cc < C_CH; cc++)
                acc = fmaf(p_rbd[base+cc], cs[cc], acc);      // tf plane
            out[OFF_TDIF + nn*60 + l] = acc;
        }
    }
    __syncthreads();   // 2b must finish before scans overwrite planes 5/6

    const float mu_direct = __ldg(&x_surface[n*5 + 0]);
    const float rs_dir    = __ldg(&x_surface[n*5 + 1]);
    const float rs_dif    = __ldg(&x_surface[n*5 + 2]);

    // ---------------- backward scan (per (n,c) chain, prefetch next layer) ----------------
    {
        float rbd = rs_dir, rbf = rs_dif;
        int idx = 59*PL_STRIDE + nbase + c;
        float td = p_td[idx], sd = p_sd[idx], rd = p_rd[idx];
        float Td = p_Td[idx], Rd = p_Rd[idx];
        for (int l = 59; l >= 0; l--) {
            const int idxn = idx - PL_STRIDE;
            float tdn=0.f, sdn=0.f, rdn=0.f, Tdn=0.f, Rdn=0.f;
            if (l > 0) {
                tdn = p_td[idxn]; sdn = p_sd[idxn]; rdn = p_rd[idxn];
                Tdn = p_Td[idxn]; Rdn = p_Rd[idxn];
            }
            float dd = frcp_nr(1.f - Rd*rbf);
            p_rbd[idx] = rbd; p_rbf[idx] = rbf;
            float rad = rd + Td*dd*(td*rbd + sd*rbf);
            float raf = Rd + Td*Td*dd*rbf;
            rbd = rad; rbf = raf;
            td = tdn; sd = sdn; rd = rdn; Td = Tdn; Rd = Rdn;
            idx = idxn;
        }
        s_rtoa[tid] = rbd * cs[c];
    }

    // ---------------- forward scan ----------------
    {
        float* q_a  = &g_planes[0][0][0];
        float* q_D  = &g_planes[1][0][0];
        float* q_up = &g_planes[2][0][0];
        float* q_ab = &g_planes[3][0][0];
        float fdir = cs[c] * mu_direct * SOLAR_C;
        float fdif = 0.f;
        int idx = nbase + c;
        float td = p_td[idx], sd = p_sd[idx], rd = p_rd[idx];
        float Td = p_Td[idx], Rd = p_Rd[idx];
        float rb0 = p_rbd[idx], rb1 = p_rbf[idx];
        for (int l = 0; l < 60; l++) {
            const int idxn = idx + PL_STRIDE;
            float tdn=0.f, sdn=0.f, rdn=0.f, Tdn=0.f, Rdn=0.f, rb0n=0.f, rb1n=0.f;
            if (l < 59) {
                tdn = p_td[idxn]; sdn = p_sd[idxn]; rdn = p_rd[idxn];
                Tdn = p_Td[idxn]; Rdn = p_Rd[idxn];
                rb0n = p_rbd[idxn]; rb1n = p_rbf[idxn];
            }
            float dd = frcp_nr(1.f - Rd*rb1);
            float a  = td * fdir;
            float D  = dd * (Td*fdif + sd*fdir + Rd*rb0*a);
            float U  = rb0*a + rb1*D;
            float up = rd*fdir + Rd*fdif + Td*U;
            float ab = fdir + fdif + U - a - D - up;
            q_a[idx] = a; q_D[idx] = D; q_up[idx] = up; q_ab[idx] = ab;
            fdir = a; fdif = D;
            td = tdn; sd = sdn; rd = rdn; Td = Tdn; Rd = Rdn;
            rb0 = rb0n; rb1 = rb1n;
            idx = idxn;
        }
        s_al[tid] = fdir; s_dl[tid] = fdif;
    }
    __syncthreads();

    // ---------------- phase 5: flux reductions ----------------
    for (int t = tid; t < NB_S*4*60; t += NTHREADS_B) {
        int s = t / 240, rem = t - s*240;
        int arr = rem / 60, l = rem - arr*60;
        int nn = blk*NB_S + s;
        const float* src = &g_planes[arr][0][0] + l*PL_STRIDE + nn*C_CH;
        float acc = 0.f;
        #pragma unroll 6
        for (int cc = 0; cc < C_CH; cc++) acc += src[cc];
        if (arr == 0)      out[OFF_FDIR + nn*61 + l + 1] = acc;
        else if (arr == 1) out[OFF_FDIF + nn*61 + l + 1] = acc;
        else if (arr == 2) out[OFF_FUP  + nn*61 + l] = acc;
        else               out[OFF_FABS + nn*60 + l] = acc;
    }

    // ---------------- per-sample finals ----------------
    if (tid < NB_S) {
        int s = tid;
        int nn = blk*NB_S + s;
        float mu  = __ldg(&x_surface[nn*5 + 0]);
        float rsd = __ldg(&x_surface[nn*5 + 1]);
        float rsf = __ldg(&x_surface[nn*5 + 2]);
        float sum_a = 0.f, sum_d = 0.f, rt = 0.f;
        for (int cc = 0; cc < C_CH; cc++) {
            sum_a += s_al[s*C_CH + cc];
            sum_d += s_dl[s*C_CH + cc];
            rt    += s_rtoa[s*C_CH + cc];
        }
        out[OFF_FDIR + nn*61]      = mu * SOLAR_C * cs_sum_s;
        out[OFF_FDIF + nn*61]      = 0.f;
        out[OFF_FUP  + nn*61 + 60] = rsd * sum_a + rsf * sum_d;
        out[OFF_RTOA + nn]         = rt;
    }
}

extern "C" void kernel_launch(void* const* d_in, const int* in_sizes, int n_in,
                              void* d_out, int out_size) {
    (void)in_sizes; (void)n_in; (void)out_size;
    cudaFuncSetAttribute(radnet_A, cudaFuncAttributeMaxDynamicSharedMemorySize,
                         (int)sizeof(SmemA));
    radnet_A<<<N_SAMPLES, NTHREADS, sizeof(SmemA)>>>(
        (const float*)d_in[0],  (const float*)d_in[1],  (const float*)d_in[2],
        (const float*)d_in[4],  (const float*)d_in[5],  (const float*)d_in[6],
        (const float*)d_in[7],  (const float*)d_in[8],  (const float*)d_in[9],
        (const float*)d_in[10], (const float*)d_in[11]);
    radnet_B<<<GRID_B, NTHREADS_B>>>(
        (const float*)d_in[1],  (const float*)d_in[3],  (float*)d_out);
}

// round 10
// speedup vs baseline: 1.6819x; 1.6819x over previous
#include <cuda_runtime.h>

// Problem constants (fixed shapes)
#define N_SAMPLES 1024
#define L_LAYERS  60
#define C_CH      42
#define NOUT      336      // C*K
#define LC        2520     // L*C
#define NTHREADS  352
#define SOLAR_C   1361.0f
#define EPSV      1e-6f

// h_t swizzled layout: row stride 80 floats, 16-layer chunk lg at offset lg*20
#define HT_STRIDE 80
#define HT_CHUNK  20

// Output offsets (tuple arrays flattened C-order, concatenated in order)
#define OFF_FDIR 0
#define OFF_FDIF (N_SAMPLES*61)
#define OFF_FUP  (2*N_SAMPLES*61)
#define OFF_FABS (3*N_SAMPLES*61)
#define OFF_RTOA (OFF_FABS + N_SAMPLES*60)
#define OFF_SDIR (OFF_RTOA + N_SAMPLES)
#define OFF_SDIF (OFF_SDIR + N_SAMPLES*60)
#define OFF_TDIR (OFF_SDIF + N_SAMPLES*60)
#define OFF_TDIF (OFF_TDIR + N_SAMPLES*60)

// Smem plane usage over time (9 planes of 2520 floats):
//  0: tau     -> td  -> a          (phase1b -> phase2 -> phase4)
//  1: h_t[0:2520)      -> sd -> D
//  2: h_t[2520:5040)   -> rd -> up
//  3: h_t[5040:5120) (80 fl) -> Td -> abs   (h_t dead before phase 2 writes Td)
//  4:            Rd
//  5:            tf   (consumed by 2b)
//  6:            es   (consumed by 2b)
//  7:            rb_dir  (written by backward scan, concurrent with 2b)
//  8:            rb_dif
struct Smem {
    float arrs[9*2520];
    float xs[600];
    float b1[64];
    float w1[128];
    float scw1_0[16];
    float beff_dir[16];
    float beff_dif[16];
    float scw2[48];
    float scb2[4];
    float cs[42];
    float cs_sum;
    float scratch[64];
};

__device__ __forceinline__ float softplus_f(float x) {
    return fmaxf(x, 0.f) + __logf(1.f + __expf(-fabsf(x)));
}
__device__ __forceinline__ float frcp(float x) {
    float r; asm("rcp.approx.ftz.f32 %0, %1;" : "=f"(r) : "f"(x)); return r;
}
// ---- packed f32x2 helpers ----
__device__ __forceinline__ unsigned long long dup2(float x) {
    unsigned long long r;
    asm("mov.b64 %0, {%1, %1};" : "=l"(r) : "f"(x));
    return r;
}
__device__ __forceinline__ unsigned long long pack2(float lo, float hi) {
    unsigned long long r;
    asm("mov.b64 %0, {%1, %2};" : "=l"(r) : "f"(lo), "f"(hi));
    return r;
}
__device__ __forceinline__ void unpack2(unsigned long long v, float& lo, float& hi) {
    asm("mov.b64 {%0, %1}, %2;" : "=f"(lo), "=f"(hi) : "l"(v));
}
__device__ __forceinline__ void ffma2(unsigned long long& d, unsigned long long a,
                                      unsigned long long b) {
    asm("fma.rn.f32x2 %0, %1, %2, %0;" : "+l"(d) : "l"(a), "l"(b));
}

__global__ __launch_bounds__(NTHREADS, 2)
void radnet_kernel(const float* __restrict__ x_layers,
                   const float* __restrict__ x_surface,
                   const float* __restrict__ w_mu,
                   const float* __restrict__ w_spec,
                   const float* __restrict__ od_w1,
                   const float* __restrict__ od_b1,
                   const float* __restrict__ od_w2,
                   const float* __restrict__ od_b2,
                   const float* __restrict__ sc_w1,
                   const float* __restrict__ sc_b1,
                   const float* __restrict__ sc_w2,
                   const float* __restrict__ sc_b2,
                   float* __restrict__ out)
{
    extern __shared__ __align__(16) char smem_raw[];
    Smem* S = reinterpret_cast<Smem*>(smem_raw);
    const int tid = threadIdx.x;
    const int n = blockIdx.x;

    const float mu_direct = __ldg(&x_surface[n*5 + 0]);
    const float rs_dir    = __ldg(&x_surface[n*5 + 1]);
    const float rs_dif    = __ldg(&x_surface[n*5 + 2]);
    const float wmu       = __ldg(&w_mu[0]);
    const float mu_dif0   = 1.f / (1.f + __expf(-wmu));
    const float inv_mud   = 1.f / (mu_direct + EPSV);
    const float inv_muf   = 1.f / (mu_dif0 + EPSV);

    // ---------------- setup ----------------
    {
        const float4* xsrc = reinterpret_cast<const float4*>(x_layers + (size_t)n * 600);
        float4* xdst = reinterpret_cast<float4*>(S->xs);
        for (int i = tid; i < 150; i += NTHREADS) xdst[i] = xsrc[i];
        if (tid < 64)  S->b1[tid] = od_b1[tid];
        if (tid >= 64 && tid < 192) S->w1[tid-64] = od_w1[tid-64];
        if (tid >= 192 && tid < 208) {
            int j = tid - 192;
            float w1c = sc_w1[j*2 + 1];
            float b   = sc_b1[j];
            S->scw1_0[j]   = sc_w1[j*2];
            S->beff_dir[j] = fmaf(w1c, mu_direct, b);
            S->beff_dif[j] = fmaf(w1c, mu_dif0, b);
        }
        if (tid >= 208 && tid < 256) S->scw2[tid-208] = sc_w2[tid-208];
        if (tid >= 256 && tid < 259) S->scb2[tid-256] = sc_b2[tid-256];
        if (tid == NTHREADS-1) {
            float m = -1e30f;
            for (int c = 0; c < C_CH; c++) m = fmaxf(m, w_spec[c]);
            float s = 0.f;
            float tmp[C_CH];
            for (int c = 0; c < C_CH; c++) { float e = __expf(w_spec[c]-m); tmp[c] = e; s += e; }
            float inv = 1.f / s;
            float cssum = 0.f;
            for (int c = 0; c < C_CH; c++) { float v = tmp[c]*inv; S->cs[c] = v; cssum += v; }
            S->cs_sum = cssum;
        }
    }
    __syncthreads();

    // ---------------- phase 1a: transposed hidden h_t, swizzled layout ----------------
    float* h_t = S->arrs + 2520;   // 5120 floats (planes 1-2 + 80 floats of plane 3)
    for (int i = tid; i < 4096; i += NTHREADS) {
        int j = i >> 6, l = i & 63;
        float v = 0.f;
        if (l < 60) {
            float pre = fmaf(S->w1[j*2],   S->xs[l*10],
                        fmaf(S->w1[j*2+1], S->xs[l*10+1], S->b1[j]));
            v = softplus_f(pre);
        }
        h_t[j*HT_STRIDE + (l>>4)*HT_CHUNK + (l&15)] = v;
    }
    __syncthreads();

    // ---------------- phase 1b: GEMM, 4 outputs x 16 layers per thread ----------------
    float* tau = S->arrs;  // plane 0
    {
        int og = tid >> 2; if (og >= 84) og -= 84;
        const int lg = tid & 3;
        const int c = og >> 1, half = og & 1;
        const int o0 = c*8 + half*4;
        const int l_base = lg << 4;
        const float4* w2r0 = reinterpret_cast<const float4*>(od_w2) + (o0    )*16;
        const float4* w2r1 = w2r0 + 16;
        const float4* w2r2 = w2r0 + 32;
        const float4* w2r3 = w2r0 + 48;
        float b2v[4];
        #pragma unroll
        for (int i = 0; i < 4; i++) b2v[i] = __ldg(&od_b2[o0+i]);
        const unsigned hbase = (unsigned)__cvta_generic_to_shared(h_t)
                             + (unsigned)(lg*HT_CHUNK*4);

        #pragma unroll 1
        for (int sub = 0; sub < 2; sub++) {
            const unsigned soff = (unsigned)(sub*32);
            unsigned long long acc0[4], acc1[4], acc2[4], acc3[4];
            #pragma unroll
            for (int p = 0; p < 4; p++) { acc0[p]=0ull; acc1[p]=0ull; acc2[p]=0ull; acc3[p]=0ull; }
            #pragma unroll 1
            for (int j4 = 0; j4 < 16; j4++) {
                float4 w0 = __ldg(&w2r0[j4]);
                float4 w1 = __ldg(&w2r1[j4]);
                float4 w2 = __ldg(&w2r2[j4]);
                float4 w3 = __ldg(&w2r3[j4]);
                #pragma unroll
                for (int jj = 0; jj < 4; jj++) {
                    const unsigned a = hbase + soff
                                     + (unsigned)((j4*4 + jj)*HT_STRIDE*4);
                    unsigned long long h0, h1, h2, h3;
                    asm("ld.shared.v2.u64 {%0, %1}, [%2];"
                        : "=l"(h0), "=l"(h1) : "r"(a));
                    asm("ld.shared.v2.u64 {%0, %1}, [%2];"
                        : "=l"(h2), "=l"(h3) : "r"(a + 16u));
                    const float s0 = (jj==0)?w0.x:(jj==1)?w0.y:(jj==2)?w0.z:w0.w;
                    const float s1 = (jj==0)?w1.x:(jj==1)?w1.y:(jj==2)?w1.z:w1.w;
                    const float s2 = (jj==0)?w2.x:(jj==1)?w2.y:(jj==2)?w2.z:w2.w;
                    const float s3 = (jj==0)?w3.x:(jj==1)?w3.y:(jj==2)?w3.z:w3.w;
                    unsigned long long d0 = dup2(s0), d1 = dup2(s1);
                    unsigned long long d2 = dup2(s2), d3 = dup2(s3);
                    ffma2(acc0[0], d0, h0); ffma2(acc0[1], d0, h1);
                    ffma2(acc0[2], d0, h2); ffma2(acc0[3], d0, h3);
                    ffma2(acc1[0], d1, h0); ffma2(acc1[1], d1, h1);
                    ffma2(acc1[2], d1, h2); ffma2(acc1[3], d1, h3);
                    ffma2(acc2[0], d2, h0); ffma2(acc2[1], d2, h1);
                    ffma2(acc2[2], d2, h2); ffma2(acc2[3], d2, h3);
                    ffma2(acc3[0], d3, h0); ffma2(acc3[1], d3, h1);
                    ffma2(acc3[2], d3, h2); ffma2(acc3[3], d3, h3);
                }
            }
            #pragma unroll
            for (int p = 0; p < 4; p++) {
                const int la = l_base + sub*8 + 2*p;
                const int lb = la + 1;
                float f0a, f0b, f1a, f1b, f2a, f2b, f3a, f3b;
                unpack2(acc0[p], f0a, f0b);
                unpack2(acc1[p], f1a, f1b);
                unpack2(acc2[p], f2a, f2b);
                unpack2(acc3[p], f3a, f3b);
                float va = 0.f, vb = 0.f;
                if (la < 60) {
                    const float* cona = &S->xs[la*10 + 2 + half*4];
                    va = softplus_f(f0a + b2v[0]) * cona[0]
                       + softplus_f(f1a + b2v[1]) * cona[1]
                       + softplus_f(f2a + b2v[2]) * cona[2]
                       + softplus_f(f3a + b2v[3]) * cona[3];
                }
                if (lb < 60) {
                    const float* conb = &S->xs[lb*10 + 2 + half*4];
                    vb = softplus_f(f0b + b2v[0]) * conb[0]
                       + softplus_f(f1b + b2v[1]) * conb[1]
                       + softplus_f(f2b + b2v[2]) * conb[2]
                       + softplus_f(f3b + b2v[3]) * conb[3];
                }
                va += __shfl_xor_sync(0xFFFFFFFFu, va, 4);
                vb += __shfl_xor_sync(0xFFFFFFFFu, vb, 4);
                if (half == 0) {
                    if (la < 60) tau[la*42 + c] = va;
                    if (lb < 60) tau[lb*42 + c] = vb;
                }
            }
        }
    }
    __syncthreads();

    // ---------------- phase 2: per-(l,c) physics + split MLPs (packed {dir,dif}) ----
    float* s_td = S->arrs + 0*2520;
    float* s_sd = S->arrs + 1*2520;
    float* s_rd = S->arrs + 2*2520;
    float* s_Td = S->arrs + 3*2520;
    float* s_Rd = S->arrs + 4*2520;
    float* s_tf = S->arrs + 5*2520;
    float* s_es = S->arrs + 6*2520;
    #pragma unroll 1
    for (int pass = 0; pass < 2; pass++) {
        float tt[4];
        #pragma unroll
        for (int r = 0; r < 4; r++) {
            int idx = tid + (pass*4 + r)*NTHREADS;
            tt[r] = tau[idx < LC ? idx : 0];
        }
        const float b20 = S->scb2[0], b21 = S->scb2[1], b22 = S->scb2[2];
        unsigned long long A0[4], A1[4], A2[4];
        #pragma unroll
        for (int r = 0; r < 4; r++) {
            A0[r] = dup2(b20); A1[r] = dup2(b21); A2[r] = dup2(b22);
        }
        #pragma unroll
        for (int j = 0; j < 16; j++) {
            float w0  = S->scw1_0[j];
            float bd  = S->beff_dir[j];
            float bf  = S->beff_dif[j];
            unsigned long long w20d = dup2(S->scw2[j]);
            unsigned long long w21d = dup2(S->scw2[16+j]);
            unsigned long long w22d = dup2(S->scw2[32+j]);
            #pragma unroll
            for (int r = 0; r < 4; r++) {
                float hp = w0 * tt[r];
                float hd = fmaxf(hp + bd, 0.f);
                float hf = fmaxf(hp + bf, 0.f);
                unsigned long long h2 = pack2(hd, hf);
                ffma2(A0[r], w20d, h2);
                ffma2(A1[r], w21d, h2);
                ffma2(A2[r], w22d, h2);
            }
        }
        #pragma unroll
        for (int r = 0; r < 4; r++) {
            int idx = tid + (pass*4 + r)*NTHREADS;
            if (idx >= LC) break;
            float a0d, a0f, a1d, a1f, a2d, a2f;
            unpack2(A0[r], a0d, a0f);
            unpack2(A1[r], a1d, a1f);
            unpack2(A2[r], a2d, a2f);
            float td = __expf(-tt[r]*inv_mud);
            float tf = __expf(-tt[r]*inv_muf);
            float m  = fmaxf(a0d, fmaxf(a1d, a2d));
            float x0 = __expf(a0d-m), x1 = __expf(a1d-m), x2 = __expf(a2d-m);
            float inv = frcp(x0+x1+x2);
            float e0d = x0*inv, e1d = x1*inv;
            m  = fmaxf(a0f, fmaxf(a1f, a2f));
            x0 = __expf(a0f-m); x1 = __expf(a1f-m); x2 = __expf(a2f-m);
            inv = frcp(x0+x1+x2);
            float e0f = x0*inv, e1f = x1*inv;
            float omtd = 1.f - td, omtf = 1.f - tf;
            s_td[idx] = td;
            s_sd[idx] = omtd*e0d;
            s_rd[idx] = omtd*e1d;
            s_Td[idx] = fmaf(omtf, e0f, tf);
            s_Rd[idx] = omtf*e1f;
            s_tf[idx] = tf;
            s_es[idx] = omtf*(e0f+e1f);
        }
    }
    __syncthreads();

    // ---------------- phase 2b (threads 0-239, warps 0-7) CONCURRENT with ----------------
    // ---------------- backward scan (threads 288-329, warps 9-10)          ----------------
    float* s_rbd = S->arrs + 7*2520;
    float* s_rbf = S->arrs + 8*2520;
    if (tid < 240) {
        int arr = tid / 60, l = tid % 60;
        int base = l*42;
        float s = 0.f;
        if (arr == 0) {
            for (int c = 0; c < C_CH; c++) s = fmaf(s_sd[base+c] + s_rd[base+c], S->cs[c], s);
            out[OFF_SDIR + n*60 + l] = s;
        } else if (arr == 1) {
            for (int c = 0; c < C_CH; c++) s = fmaf(s_es[base+c], S->cs[c], s);
            out[OFF_SDIF + n*60 + l] = s;
        } else if (arr == 2) {
            for (int c = 0; c < C_CH; c++) s = fmaf(s_td[base+c], S->cs[c], s);
            out[OFF_TDIR + n*60 + l] = s;
        } else {
            for (int c = 0; c < C_CH; c++) s = fmaf(s_tf[base+c], S->cs[c], s);
            out[OFF_TDIF + n*60 + l] = s;
        }
    } else if (tid >= 288 && tid < 288 + C_CH) {
        const int c = tid - 288;
        float rbd = rs_dir, rbf = rs_dif;
        int idx = 59*42 + c;
        float td = s_td[idx], sd = s_sd[idx], rd = s_rd[idx];
        float Td = s_Td[idx], Rd = s_Rd[idx];
        for (int l = 59; l >= 0; l--) {
            const int idxn = idx - 42;
            float tdn=0.f, sdn=0.f, rdn=0.f, Tdn=0.f, Rdn=0.f;
            if (l > 0) {
                tdn = s_td[idxn]; sdn = s_sd[idxn]; rdn = s_rd[idxn];
                Tdn = s_Td[idxn]; Rdn = s_Rd[idxn];
            }
            float dd = frcp(1.f - Rd*rbf);
            s_rbd[idx] = rbd; s_rbf[idx] = rbf;
            float rad = rd + Td*dd*(td*rbd + sd*rbf);
            float raf = Rd + Td*Td*dd*rbf;
            rbd = rad; rbf = raf;
            td = tdn; sd = sdn; rd = rdn; Td = Tdn; Rd = Rdn;
            idx = idxn;
        }
        S->scratch[c] = rbd * S->cs[c];
    }
    __syncthreads();

    // ---------------- phase 4: forward scan (threads 0-41), prefetched ----------------
    if (tid < C_CH) {
        const int c = tid;
        float fdir = S->cs[c] * mu_direct * SOLAR_C;
        float fdif = 0.f;
        int idx = c;
        float td = s_td[idx], sd = s_sd[idx], rd = s_rd[idx];
        float Td = s_Td[idx], Rd = s_Rd[idx];
        float rb0 = s_rbd[idx], rb1 = s_rbf[idx];
        for (int l = 0; l < 60; l++) {
            const int idxn = idx + 42;
            float tdn=0.f, sdn=0.f, rdn=0.f, Tdn=0.f, Rdn=0.f, rb0n=0.f, rb1n=0.f;
            if (l < 59) {
                tdn = s_td[idxn]; sdn = s_sd[idxn]; rdn = s_rd[idxn];
                Tdn = s_Td[idxn]; Rdn = s_Rd[idxn];
                rb0n = s_rbd[idxn]; rb1n = s_rbf[idxn];
            }
            float dd = frcp(1.f - Rd*rb1);
            float a  = td * fdir;
            float D  = dd * (Td*fdif + sd*fdir + Rd*rb0*a);
            float U  = rb0*a + rb1*D;
            float up = rd*fdir + Rd*fdif + Td*U;
            float ab = fdir + fdif + U - a - D - up;
            s_td[idx] = a; s_sd[idx] = D; s_rd[idx] = up; s_Td[idx] = ab;
            fdir = a; fdif = D;
            td = tdn; sd = sdn; rd = rdn; Td = Tdn; Rd = Rdn;
            rb0 = rb0n; rb1 = rb1n;
            idx = idxn;
        }
    }
    __syncthreads();

    // ---------------- phase 5: flux reductions over channels ----------------
    if (tid < 240) {
        int arr = tid / 60, l = tid % 60;
        const float* src = S->arrs + arr*2520 + l*42;
        float s = 0.f;
        #pragma unroll 6
        for (int c = 0; c < C_CH; c++) s += src[c];
        if (arr == 0)      { out[OFF_FDIR + n*61 + l + 1] = s; if (l == 59) S->scratch[48] = s; }
        else if (arr == 1) { out[OFF_FDIF + n*61 + l + 1] = s; if (l == 59) S->scratch[49] = s; }
        else if (arr == 2) { out[OFF_FUP  + n*61 + l] = s; }
        else               { out[OFF_FABS + n*60 + l] = s; }
    }
    __syncthreads();

    if (tid == 0) {
        out[OFF_FDIR + n*61]      = mu_direct * SOLAR_C * S->cs_sum;
        out[OFF_FDIF + n*61]      = 0.f;
        out[OFF_FUP  + n*61 + 60] = rs_dir * S->scratch[48] + rs_dif * S->scratch[49];
        float rt = 0.f;
        for (int c = 0; c < C_CH; c++) rt += S->scratch[c];
        out[OFF_RTOA + n] = rt;
    }
}

extern "C" void kernel_launch(void* const* d_in, const int* in_sizes, int n_in,
                              void* d_out, int out_size) {
    (void)in_sizes; (void)n_in; (void)out_size;
    cudaFuncSetAttribute(radnet_kernel, cudaFuncAttributeMaxDynamicSharedMemorySize,
                         (int)sizeof(Smem));
    radnet_kernel<<<N_SAMPLES, NTHREADS, sizeof(Smem)>>>(
        (const float*)d_in[0],  (const float*)d_in[1],  (const float*)d_in[2],
        (const float*)d_in[3],  (const float*)d_in[4],  (const float*)d_in[5],
        (const float*)d_in[6],  (const float*)d_in[7],  (const float*)d_in[8],
        (const float*)d_in[9],  (const float*)d_in[10], (const float*)d_in[11],
        (float*)d_out);
}